// round 10
// baseline (speedup 1.0000x reference)
#include <cuda_runtime.h>
#include <cuda_bf16.h>
#include <math.h>

#define Bq 64
#define Nn 1024
#define Ee 16384
#define Ff 128
#define Hh 64
#define Tt 10
#define BN (Bq*Nn)   // 65536

// ---------------- scratch (static device globals; no allocs allowed) --------
__device__ __nv_bfloat16 g_A[BN*Hh]; // layer1: bf16 invs[n]*(x@W1)[n]
__device__ int      g_csr[Bq*Ee];    // CSR-by-dst: global src ids
__device__ int      g_off[BN];       // absolute start offset into g_csr
__device__ int      g_indeg[BN];
__device__ unsigned g_mask[BN];      // 10-bit token->node mask
__device__ float    g_invs[BN];      // 1/sqrt(deg_node)
__device__ float    g_w[BN];         // invs[n]*(w[n]+invs[n]) pooling weight
__device__ float    g_tm[Bq*Tt];     // tmask[g][t] = sum_n mask[n,t]*invs[n]
__device__ float    g_st1[Tt*Hh];    // invsT[t] * (tokens@W1)[t,:]   (layer1 cross)
__device__ float    g_st2p[Tt*Hh];   // invsT[t] * h1a_tok[t,:]       (layer2 cross, pre-W2)
__device__ float    g_toksum[Hh];    // sum_t out_tok2[t,:]
__device__ float    g_P[Bq*Hh];      // pooled pre-W2 node vectors (atomic accum)

// ---- helpers ----------------------------------------------------------------
__device__ __forceinline__ void acc_bf16x4(float4& a, uint2 v) {
    a.x += __uint_as_float(v.x << 16);
    a.y += __uint_as_float(v.x & 0xffff0000u);
    a.z += __uint_as_float(v.y << 16);
    a.w += __uint_as_float(v.y & 0xffff0000u);
}
__device__ __forceinline__ unsigned pack_bf16x2(float a, float b) {
    __nv_bfloat162 p = __float22bfloat162_rn(make_float2(a, b));
    return *reinterpret_cast<unsigned*>(&p);
}

// ---------------- CSR build (blocks 0-63) + token stream (block 64) ---------
__global__ void csr_token_kernel(const int* __restrict__ esrc, const int* __restrict__ edst,
                                 const float* __restrict__ tok,
                                 const float* __restrict__ W1, const float* __restrict__ b1,
                                 const float* __restrict__ W2, const float* __restrict__ b2)
{
    __shared__ union {
        struct { int cnt[Nn]; int wsum[32]; } c;
        struct {
            float tk[Tt][129];
            float nrm[Tt][Tt];
            float invsT[Tt], invdT[Tt];
            float h1l[Tt][Hh], h1a[Tt][Hh], h2l[Tt][Hh], ot2[Tt][Hh];
        } t;
    } u;
    int tid = threadIdx.x;

    if (blockIdx.x < Bq) {
        int b = blockIdx.x;
        int lane = tid & 31, wid = tid >> 5;
        u.c.cnt[tid] = 0;
        __syncthreads();
        const int* dp = edst + b*Ee;
        const int* sp = esrc + b*Ee;
        for (int e = tid; e < Ee; e += Nn) atomicAdd(&u.c.cnt[dp[e]], 1);
        __syncthreads();
        int c = u.c.cnt[tid];
        g_indeg[b*Nn + tid] = c;
        int v = c;
        for (int d = 1; d < 32; d <<= 1) {
            int uu = __shfl_up_sync(0xffffffffu, v, d);
            if (lane >= d) v += uu;
        }
        if (lane == 31) u.c.wsum[wid] = v;
        __syncthreads();
        if (tid < 32) {
            int s = u.c.wsum[tid];
            for (int d = 1; d < 32; d <<= 1) {
                int uu = __shfl_up_sync(0xffffffffu, s, d);
                if (tid >= d) s += uu;
            }
            u.c.wsum[tid] = s;
        }
        __syncthreads();
        int base = wid ? u.c.wsum[wid-1] : 0;
        int pos0 = b*Ee + base + (v - c);
        g_off[b*Nn + tid] = pos0;
        __syncthreads();
        u.c.cnt[tid] = pos0;
        __syncthreads();
        for (int e = tid; e < Ee; e += Nn) {
            int d = dp[e];
            int p = atomicAdd(&u.c.cnt[d], 1);
            g_csr[p] = b*Nn + sp[e];
        }
    } else {
        const int NT = 1024;
        for (int i = tid; i < Tt*Ff; i += NT) u.t.tk[i/Ff][i%Ff] = tok[i];
        __syncthreads();
        if (tid < Tt*Tt) {
            int i = tid/Tt, j = tid%Tt;
            float d = 0.f;
            for (int f = 0; f < Ff; f++) d += u.t.tk[i][f]*u.t.tk[j][f];
            float s = 1.f/(1.f+expf(-d));
            u.t.nrm[i][j] = (s >= 0.3f) ? 1.f : 0.f;
        }
        __syncthreads();
        if (tid < Tt) {
            float deg = 1.f;
            for (int i = 0; i < Tt; i++) deg += u.t.nrm[i][tid];
            u.t.invsT[tid] = rsqrtf(deg);
            u.t.invdT[tid] = 1.f/deg;
        }
        __syncthreads();
        if (tid < Tt*Tt) {
            int i = tid/Tt, j = tid%Tt;
            u.t.nrm[i][j] *= u.t.invsT[i]*u.t.invsT[j];
        }
        for (int idx = tid; idx < Tt*Hh; idx += NT) {
            int t = idx/Hh, h = idx%Hh;
            float a = 0.f;
            for (int f = 0; f < Ff; f++) a += u.t.tk[t][f]*W1[f*Hh+h];
            u.t.h1l[t][h] = a;
        }
        __syncthreads();
        for (int idx = tid; idx < Tt*Hh; idx += NT) {
            int t = idx/Hh, h = idx%Hh;
            float a = u.t.h1l[t][h]*u.t.invdT[t] + b1[h];
            for (int j = 0; j < Tt; j++) a += u.t.nrm[t][j]*u.t.h1l[j][h];
            float act = (a >= 0.f) ? a : 0.01f*a;
            u.t.h1a[t][h] = act;
            g_st1[idx]  = u.t.invsT[t]*u.t.h1l[t][h];
            g_st2p[idx] = u.t.invsT[t]*act;
        }
        __syncthreads();
        for (int idx = tid; idx < Tt*Hh; idx += NT) {
            int t = idx/Hh, h = idx%Hh;
            float a = 0.f;
            for (int k = 0; k < Hh; k++) a += u.t.h1a[t][k]*W2[k*Hh+h];
            u.t.h2l[t][h] = a;
        }
        __syncthreads();
        for (int idx = tid; idx < Tt*Hh; idx += NT) {
            int t = idx/Hh, h = idx%Hh;
            float a = u.t.h2l[t][h]*u.t.invdT[t] + b2[h];
            for (int j = 0; j < Tt; j++) a += u.t.nrm[t][j]*u.t.h2l[j][h];
            u.t.ot2[t][h] = a;
        }
        __syncthreads();
        if (tid < Hh) {
            float s = 0.f;
            for (int t = 0; t < Tt; t++) s += u.t.ot2[t][tid];
            g_toksum[tid] = s;
        }
        for (int i = tid; i < Bq*Hh; i += NT) g_P[i] = 0.f;
    }
}

// ------- fused x-pass: tf32 MMA for x@W1, fp32 token dots -> mask, deg ------
__global__ void xpass_kernel(const float* __restrict__ x, const float* __restrict__ W1,
                             const float* __restrict__ tok)
{
    __shared__ float xs2[64][68];         // x chunk row-major [n][f]
    __shared__ float ws[64][68];          // W1 chunk [f][h] (padded rows)
    __shared__ float ts[Tt][64];          // tokens chunk [t][f]
    __shared__ unsigned maskbuf[64];
    __shared__ float invsS[64];
    int tid = threadIdx.x;
    int bn0 = blockIdx.x * 64;
    int w = tid >> 5, t = tid & 31;
    int m0 = (w & 3) * 16;
    int h0 = (w >> 2) * 32;
    int ty = t >> 2, tk = t & 3;

    float acc[4][4];
    #pragma unroll
    for (int i = 0; i < 4; i++)
        #pragma unroll
        for (int j = 0; j < 4; j++) acc[i][j] = 0.f;
    float dacc[3] = {0.f, 0.f, 0.f};
    if (tid < 64) maskbuf[tid] = 0u;

    for (int c = 0; c < 2; c++) {
        __syncthreads();
        for (int idx = tid; idx < 4096; idx += 256) {
            int f = idx & 63, n = idx >> 6;
            xs2[n][f] = x[(bn0+n)*Ff + c*64 + f];
        }
        for (int idx = tid; idx < 4096; idx += 256) {
            int h = idx & 63, f = idx >> 6;
            ws[f][h] = W1[(c*64+f)*Hh + h];
        }
        for (int idx = tid; idx < Tt*64; idx += 256) {
            int f = idx & 63, tt = idx >> 6;
            ts[tt][f] = tok[tt*Ff + c*64 + f];
        }
        __syncthreads();
        #pragma unroll
        for (int r = 0; r < 3; r++) {
            int idx = tid + r*256;
            if (idx < 640) {
                int n = idx & 63, tt = idx >> 6;
                float a = dacc[r];
                #pragma unroll 8
                for (int f = 0; f < 64; f++) a += xs2[n][f]*ts[tt][f];
                dacc[r] = a;
            }
        }
        #pragma unroll
        for (int k8 = 0; k8 < 8; k8++) {
            int k0 = k8*8;
            unsigned a0 = __float_as_uint(xs2[m0+ty  ][k0+tk  ]);
            unsigned a1 = __float_as_uint(xs2[m0+ty+8][k0+tk  ]);
            unsigned a2 = __float_as_uint(xs2[m0+ty  ][k0+tk+4]);
            unsigned a3 = __float_as_uint(xs2[m0+ty+8][k0+tk+4]);
            #pragma unroll
            for (int ns = 0; ns < 4; ns++) {
                unsigned b0 = __float_as_uint(ws[k0+tk  ][h0+ns*8+ty]);
                unsigned b1 = __float_as_uint(ws[k0+tk+4][h0+ns*8+ty]);
                asm volatile(
                    "mma.sync.aligned.m16n8k8.row.col.f32.tf32.tf32.f32 "
                    "{%0,%1,%2,%3},{%4,%5,%6,%7},{%8,%9},{%0,%1,%2,%3};"
                    : "+f"(acc[ns][0]), "+f"(acc[ns][1]),
                      "+f"(acc[ns][2]), "+f"(acc[ns][3])
                    : "r"(a0), "r"(a1), "r"(a2), "r"(a3), "r"(b0), "r"(b1));
            }
        }
    }
    #pragma unroll
    for (int r = 0; r < 3; r++) {
        int idx = tid + r*256;
        if (idx < 640) {
            int n = idx & 63, tt = idx >> 6;
            float s = 1.f/(1.f+expf(-dacc[r]));
            if (s >= 0.1f) atomicOr(&maskbuf[n], 1u << tt);
        }
    }
    __syncthreads();
    if (tid < 64) {
        int bn = bn0 + tid;
        unsigned m = maskbuf[tid];
        float deg = 1.0f + (float)g_indeg[bn] + (float)__popc(m);
        float is = rsqrtf(deg);
        g_mask[bn] = m;
        g_invs[bn] = is;
        invsS[tid] = is;
    }
    __syncthreads();
    {
        unsigned* A32 = (unsigned*)g_A;
        int r0 = m0 + ty, r1 = r0 + 8;
        float s0 = invsS[r0], s1 = invsS[r1];
        int cb = (h0 >> 1) + tk;
        #pragma unroll
        for (int ns = 0; ns < 4; ns++) {
            A32[(bn0+r0)*32 + cb + ns*4] = pack_bf16x2(acc[ns][0]*s0, acc[ns][1]*s0);
            A32[(bn0+r1)*32 + cb + ns*4] = pack_bf16x2(acc[ns][2]*s1, acc[ns][3]*s1);
        }
    }
}

// ------- per-graph source weights + token-mask sums -------------------------
// w[s] = sum over edges s->n of invs[n];  g_w[s] = invs[s]*(w[s]+invs[s])
// g_tm[g][t] = sum_n mask[n][t]*invs[n]
__global__ void wtok_kernel(const int* __restrict__ esrc, const int* __restrict__ edst)
{
    __shared__ float invs_s[Nn];
    __shared__ float w_s[Nn];
    __shared__ float tm[Tt];
    int g = blockIdx.x, tid = threadIdx.x;
    int lane = tid & 31;
    invs_s[tid] = g_invs[g*Nn + tid];
    w_s[tid] = 0.f;
    if (tid < Tt) tm[tid] = 0.f;
    __syncthreads();
    const int* sp = esrc + g*Ee;
    const int* dp = edst + g*Ee;
    for (int e = tid; e < Ee; e += Nn)
        atomicAdd(&w_s[sp[e]], invs_s[dp[e]]);
    // token-mask weighted sums: warp shuffle reduce then smem atomic
    {
        unsigned m = g_mask[g*Nn + tid];
        float v = invs_s[tid];
        #pragma unroll
        for (int t = 0; t < Tt; t++) {
            float p = ((m >> t) & 1u) ? v : 0.f;
            #pragma unroll
            for (int d = 16; d > 0; d >>= 1)
                p += __shfl_xor_sync(0xffffffffu, p, d);
            if (lane == 0) atomicAdd(&tm[t], p);
        }
    }
    __syncthreads();
    g_w[g*Nn + tid] = invs_s[tid]*(w_s[tid] + invs_s[tid]);
    if (tid < Tt) g_tm[g*Tt + tid] = tm[tid];
}

// ---- gather core: R4/R6 proven load pattern (scalar idx, fp32 accumulate) --
__device__ __forceinline__ float4 gather_node(const uint2* __restrict__ A2,
                                              int bn, int l16, int half)
{
    int cnt = g_indeg[bn];
    int off = g_off[bn];
    float4 acc = make_float4(0.f, 0.f, 0.f, 0.f);
    int e = 0;
    for (; e + 8 <= cnt; e += 8) {
        int i0 = __ldg(&g_csr[off + e     + half]);
        int i1 = __ldg(&g_csr[off + e + 2 + half]);
        int i2 = __ldg(&g_csr[off + e + 4 + half]);
        int i3 = __ldg(&g_csr[off + e + 6 + half]);
        uint2 v0 = __ldg(&A2[i0*16 + l16]);
        uint2 v1 = __ldg(&A2[i1*16 + l16]);
        uint2 v2 = __ldg(&A2[i2*16 + l16]);
        uint2 v3 = __ldg(&A2[i3*16 + l16]);
        acc_bf16x4(acc, v0); acc_bf16x4(acc, v1);
        acc_bf16x4(acc, v2); acc_bf16x4(acc, v3);
    }
    for (; e + 2 <= cnt; e += 2) {
        int i0 = __ldg(&g_csr[off + e + half]);
        uint2 v0 = __ldg(&A2[i0*16 + l16]);
        acc_bf16x4(acc, v0);
    }
    if (e < cnt && half == 0) {
        int i0 = __ldg(&g_csr[off + e]);
        uint2 v0 = __ldg(&A2[i0*16 + l16]);
        acc_bf16x4(acc, v0);
    }
    acc.x += __shfl_xor_sync(0xffffffffu, acc.x, 16);
    acc.y += __shfl_xor_sync(0xffffffffu, acc.y, 16);
    acc.z += __shfl_xor_sync(0xffffffffu, acc.z, 16);
    acc.w += __shfl_xor_sync(0xffffffffu, acc.w, 16);
    return acc;
}

// ------- agg1 (final node kernel): layer-1 gather + act + weighted pool -----
__global__ void agg1_kernel(const float* __restrict__ b1)
{
    __shared__ float4 st[Tt*16];
    __shared__ float4 bias[16];
    __shared__ float sum[Hh];
    int tid = threadIdx.x;
    const float4* s1p = (const float4*)g_st1;
    for (int i = tid; i < Tt*16; i += 256) st[i] = s1p[i];
    if (tid < 16) bias[tid] = ((const float4*)b1)[tid];
    if (tid < Hh) sum[tid] = 0.f;
    __syncthreads();
    int lane = tid & 31;
    int l16 = lane & 15, half = lane >> 4;
    int bn = blockIdx.x*8 + (tid >> 5);
    float4 acc = gather_node((const uint2*)g_A, bn, l16, half);
    if (half == 0) {
        unsigned mk = g_mask[bn];
        while (mk) {
            int t = __ffs(mk) - 1; mk &= mk - 1;
            float4 v = st[t*16 + l16];
            acc.x += v.x; acc.y += v.y; acc.z += v.z; acc.w += v.w;
        }
        uint2 sv = ((const uint2*)g_A)[bn*16 + l16];
        acc_bf16x4(acc, sv);
        float is = g_invs[bn];
        float4 bb = bias[l16];
        float4 o;
        o.x = acc.x*is + bb.x; o.y = acc.y*is + bb.y;
        o.z = acc.z*is + bb.z; o.w = acc.w*is + bb.w;
        o.x = (o.x >= 0.f) ? o.x : 0.01f*o.x;
        o.y = (o.y >= 0.f) ? o.y : 0.01f*o.y;
        o.z = (o.z >= 0.f) ? o.z : 0.01f*o.z;
        o.w = (o.w >= 0.f) ? o.w : 0.01f*o.w;
        // weighted pool contribution: act1[n] * invs[n]*(w[n]+invs[n])
        float fw = g_w[bn];
        atomicAdd(&sum[l16*4+0], o.x*fw);
        atomicAdd(&sum[l16*4+1], o.y*fw);
        atomicAdd(&sum[l16*4+2], o.z*fw);
        atomicAdd(&sum[l16*4+3], o.w*fw);
    }
    __syncthreads();
    if (tid < Hh) {
        int b = blockIdx.x >> 7;            // 128 blocks per graph
        atomicAdd(&g_P[b*Hh + tid], sum[tid]);
    }
}

// ------- head: add token-cross, W2 matvec, b2/toksum, pool, softmax ---------
__global__ void head_kernel(const float* __restrict__ W2, const float* __restrict__ b2,
                            const float* __restrict__ Wa, const float* __restrict__ ba,
                            float* __restrict__ out)
{
    __shared__ float P[Hh];
    __shared__ float emb[Hh];
    __shared__ float tm[Tt];
    int g = blockIdx.x, h = threadIdx.x;
    if (h < Tt) tm[h] = g_tm[g*Tt + h];
    __syncthreads();
    float p = g_P[g*Hh + h];
    #pragma unroll
    for (int t = 0; t < Tt; t++) p += g_st2p[t*Hh + h]*tm[t];
    P[h] = p;
    __syncthreads();
    const float scale = 1.f/(float)(Tt + Nn);
    float a = 0.f;
    for (int k = 0; k < Hh; k++) a += P[k]*W2[k*Hh + h];
    emb[h] = (a + (float)Nn*b2[h] + g_toksum[h]) * scale;
    __syncthreads();
    if (h == 0) {
        float l0 = ba[0], l1 = ba[1];
        for (int o = 0; o < Hh; o++) {
            l0 += emb[o]*Wa[o*2+0];
            l1 += emb[o]*Wa[o*2+1];
        }
        float mx = fmaxf(l0, l1);
        float e0 = expf(l0 - mx), e1 = expf(l1 - mx);
        float s = e0 + e1;
        out[g*2+0] = e0/s;
        out[g*2+1] = e1/s;
    }
}

// ---------------- launch ----------------------------------------------------
extern "C" void kernel_launch(void* const* d_in, const int* in_sizes, int n_in,
                              void* d_out, int out_size)
{
    const float* x    = (const float*)d_in[0];
    const float* tok  = (const float*)d_in[1];
    const float* W1   = (const float*)d_in[2];
    const float* b1   = (const float*)d_in[3];
    const float* W2   = (const float*)d_in[4];
    const float* b2   = (const float*)d_in[5];
    const float* Wa   = (const float*)d_in[6];
    const float* ba   = (const float*)d_in[7];
    const int*   esrc = (const int*)d_in[8];
    const int*   edst = (const int*)d_in[9];
    float* out = (float*)d_out;

    csr_token_kernel<<<Bq + 1, Nn>>>(esrc, edst, tok, W1, b1, W2, b2);
    xpass_kernel<<<BN/64, 256>>>(x, W1, tok);
    wtok_kernel<<<Bq, Nn>>>(esrc, edst);
    agg1_kernel<<<BN/8, 256>>>(b1);
    head_kernel<<<Bq, Hh>>>(W2, b2, Wa, ba, out);
}

// round 11
// speedup vs baseline: 1.5175x; 1.5175x over previous
#include <cuda_runtime.h>
#include <cuda_bf16.h>
#include <math.h>

#define Bq 64
#define Nn 1024
#define Ee 16384
#define Ff 128
#define Hh 64
#define Tt 10
#define BN (Bq*Nn)   // 65536

// ---------------- scratch (static device globals; no allocs allowed) --------
__device__ __nv_bfloat16 g_A[BN*Hh]; // layer1: bf16 invs[n]*(x@W1)[n]
__device__ int      g_csr[Bq*Ee];    // CSR-by-dst: global src ids
__device__ int      g_off[BN];       // absolute start offset into g_csr
__device__ int      g_indeg[BN];
__device__ unsigned g_mask[BN];      // 10-bit token->node mask
__device__ float    g_invs[BN];      // 1/sqrt(deg_node)
__device__ float    g_w[BN];         // invs[n]*(w[n]+invs[n]) pooling weight
__device__ float    g_tm[Bq*Tt];     // tmask[g][t] = sum_n mask[n,t]*invs[n]
__device__ float    g_st1[Tt*Hh];    // invsT[t] * (tokens@W1)[t,:]   (layer1 cross)
__device__ float    g_st2p[Tt*Hh];   // invsT[t] * h1a_tok[t,:]       (layer2 cross, pre-W2)
__device__ float    g_toksum[Hh];    // sum_t out_tok2[t,:]
__device__ float    g_P[Bq*Hh];      // pooled pre-W2 node vectors (atomic accum)

// ---- helpers ----------------------------------------------------------------
__device__ __forceinline__ void acc_bf16x4(float4& a, uint2 v) {
    a.x += __uint_as_float(v.x << 16);
    a.y += __uint_as_float(v.x & 0xffff0000u);
    a.z += __uint_as_float(v.y << 16);
    a.w += __uint_as_float(v.y & 0xffff0000u);
}
__device__ __forceinline__ unsigned pack_bf16x2(float a, float b) {
    __nv_bfloat162 p = __float22bfloat162_rn(make_float2(a, b));
    return *reinterpret_cast<unsigned*>(&p);
}

// ---------------- CSR build (blocks 0-63) + token stream (block 64) ---------
__global__ void csr_token_kernel(const int* __restrict__ esrc, const int* __restrict__ edst,
                                 const float* __restrict__ tok,
                                 const float* __restrict__ W1, const float* __restrict__ b1,
                                 const float* __restrict__ W2, const float* __restrict__ b2)
{
    __shared__ union {
        struct { int cnt[Nn]; int wsum[32]; } c;
        struct {
            float tk[Tt][129];
            float nrm[Tt][Tt];
            float invsT[Tt], invdT[Tt];
            float h1l[Tt][Hh], h1a[Tt][Hh], h2l[Tt][Hh], ot2[Tt][Hh];
        } t;
    } u;
    int tid = threadIdx.x;

    if (blockIdx.x < Bq) {
        int b = blockIdx.x;
        int lane = tid & 31, wid = tid >> 5;
        u.c.cnt[tid] = 0;
        __syncthreads();
        const int* dp = edst + b*Ee;
        const int* sp = esrc + b*Ee;
        for (int e = tid; e < Ee; e += Nn) atomicAdd(&u.c.cnt[dp[e]], 1);
        __syncthreads();
        int c = u.c.cnt[tid];
        g_indeg[b*Nn + tid] = c;
        int v = c;
        for (int d = 1; d < 32; d <<= 1) {
            int uu = __shfl_up_sync(0xffffffffu, v, d);
            if (lane >= d) v += uu;
        }
        if (lane == 31) u.c.wsum[wid] = v;
        __syncthreads();
        if (tid < 32) {
            int s = u.c.wsum[tid];
            for (int d = 1; d < 32; d <<= 1) {
                int uu = __shfl_up_sync(0xffffffffu, s, d);
                if (tid >= d) s += uu;
            }
            u.c.wsum[tid] = s;
        }
        __syncthreads();
        int base = wid ? u.c.wsum[wid-1] : 0;
        int pos0 = b*Ee + base + (v - c);
        g_off[b*Nn + tid] = pos0;
        __syncthreads();
        u.c.cnt[tid] = pos0;
        __syncthreads();
        for (int e = tid; e < Ee; e += Nn) {
            int d = dp[e];
            int p = atomicAdd(&u.c.cnt[d], 1);
            g_csr[p] = b*Nn + sp[e];
        }
    } else {
        const int NT = 1024;
        for (int i = tid; i < Tt*Ff; i += NT) u.t.tk[i/Ff][i%Ff] = tok[i];
        __syncthreads();
        if (tid < Tt*Tt) {
            int i = tid/Tt, j = tid%Tt;
            float d = 0.f;
            for (int f = 0; f < Ff; f++) d += u.t.tk[i][f]*u.t.tk[j][f];
            float s = 1.f/(1.f+expf(-d));
            u.t.nrm[i][j] = (s >= 0.3f) ? 1.f : 0.f;
        }
        __syncthreads();
        if (tid < Tt) {
            float deg = 1.f;
            for (int i = 0; i < Tt; i++) deg += u.t.nrm[i][tid];
            u.t.invsT[tid] = rsqrtf(deg);
            u.t.invdT[tid] = 1.f/deg;
        }
        __syncthreads();
        if (tid < Tt*Tt) {
            int i = tid/Tt, j = tid%Tt;
            u.t.nrm[i][j] *= u.t.invsT[i]*u.t.invsT[j];
        }
        for (int idx = tid; idx < Tt*Hh; idx += NT) {
            int t = idx/Hh, h = idx%Hh;
            float a = 0.f;
            for (int f = 0; f < Ff; f++) a += u.t.tk[t][f]*W1[f*Hh+h];
            u.t.h1l[t][h] = a;
        }
        __syncthreads();
        for (int idx = tid; idx < Tt*Hh; idx += NT) {
            int t = idx/Hh, h = idx%Hh;
            float a = u.t.h1l[t][h]*u.t.invdT[t] + b1[h];
            for (int j = 0; j < Tt; j++) a += u.t.nrm[t][j]*u.t.h1l[j][h];
            float act = (a >= 0.f) ? a : 0.01f*a;
            u.t.h1a[t][h] = act;
            g_st1[idx]  = u.t.invsT[t]*u.t.h1l[t][h];
            g_st2p[idx] = u.t.invsT[t]*act;
        }
        __syncthreads();
        for (int idx = tid; idx < Tt*Hh; idx += NT) {
            int t = idx/Hh, h = idx%Hh;
            float a = 0.f;
            for (int k = 0; k < Hh; k++) a += u.t.h1a[t][k]*W2[k*Hh+h];
            u.t.h2l[t][h] = a;
        }
        __syncthreads();
        for (int idx = tid; idx < Tt*Hh; idx += NT) {
            int t = idx/Hh, h = idx%Hh;
            float a = u.t.h2l[t][h]*u.t.invdT[t] + b2[h];
            for (int j = 0; j < Tt; j++) a += u.t.nrm[t][j]*u.t.h2l[j][h];
            u.t.ot2[t][h] = a;
        }
        __syncthreads();
        if (tid < Hh) {
            float s = 0.f;
            for (int t = 0; t < Tt; t++) s += u.t.ot2[t][tid];
            g_toksum[tid] = s;
        }
        for (int i = tid; i < Bq*Hh; i += NT) g_P[i] = 0.f;
    }
}

// ------- fused x-pass: tf32 MMA for x@W1, fp32 token dots -> mask, deg ------
__global__ void xpass_kernel(const float* __restrict__ x, const float* __restrict__ W1,
                             const float* __restrict__ tok)
{
    __shared__ float xs2[64][68];         // x chunk row-major [n][f]
    __shared__ float ws[64][68];          // W1 chunk [f][h] (padded rows)
    __shared__ float ts[Tt][64];          // tokens chunk [t][f]
    __shared__ unsigned maskbuf[64];
    __shared__ float invsS[64];
    int tid = threadIdx.x;
    int bn0 = blockIdx.x * 64;
    int w = tid >> 5, t = tid & 31;
    int m0 = (w & 3) * 16;
    int h0 = (w >> 2) * 32;
    int ty = t >> 2, tk = t & 3;

    float acc[4][4];
    #pragma unroll
    for (int i = 0; i < 4; i++)
        #pragma unroll
        for (int j = 0; j < 4; j++) acc[i][j] = 0.f;
    float dacc[3] = {0.f, 0.f, 0.f};
    if (tid < 64) maskbuf[tid] = 0u;

    for (int c = 0; c < 2; c++) {
        __syncthreads();
        for (int idx = tid; idx < 4096; idx += 256) {
            int f = idx & 63, n = idx >> 6;
            xs2[n][f] = x[(bn0+n)*Ff + c*64 + f];
        }
        for (int idx = tid; idx < 4096; idx += 256) {
            int h = idx & 63, f = idx >> 6;
            ws[f][h] = W1[(c*64+f)*Hh + h];
        }
        for (int idx = tid; idx < Tt*64; idx += 256) {
            int f = idx & 63, tt = idx >> 6;
            ts[tt][f] = tok[tt*Ff + c*64 + f];
        }
        __syncthreads();
        #pragma unroll
        for (int r = 0; r < 3; r++) {
            int idx = tid + r*256;
            if (idx < 640) {
                int n = idx & 63, tt = idx >> 6;
                float a = dacc[r];
                #pragma unroll 8
                for (int f = 0; f < 64; f++) a += xs2[n][f]*ts[tt][f];
                dacc[r] = a;
            }
        }
        #pragma unroll
        for (int k8 = 0; k8 < 8; k8++) {
            int k0 = k8*8;
            unsigned a0 = __float_as_uint(xs2[m0+ty  ][k0+tk  ]);
            unsigned a1 = __float_as_uint(xs2[m0+ty+8][k0+tk  ]);
            unsigned a2 = __float_as_uint(xs2[m0+ty  ][k0+tk+4]);
            unsigned a3 = __float_as_uint(xs2[m0+ty+8][k0+tk+4]);
            #pragma unroll
            for (int ns = 0; ns < 4; ns++) {
                unsigned b0 = __float_as_uint(ws[k0+tk  ][h0+ns*8+ty]);
                unsigned b1 = __float_as_uint(ws[k0+tk+4][h0+ns*8+ty]);
                asm volatile(
                    "mma.sync.aligned.m16n8k8.row.col.f32.tf32.tf32.f32 "
                    "{%0,%1,%2,%3},{%4,%5,%6,%7},{%8,%9},{%0,%1,%2,%3};"
                    : "+f"(acc[ns][0]), "+f"(acc[ns][1]),
                      "+f"(acc[ns][2]), "+f"(acc[ns][3])
                    : "r"(a0), "r"(a1), "r"(a2), "r"(a3), "r"(b0), "r"(b1));
            }
        }
    }
    #pragma unroll
    for (int r = 0; r < 3; r++) {
        int idx = tid + r*256;
        if (idx < 640) {
            int n = idx & 63, tt = idx >> 6;
            float s = 1.f/(1.f+expf(-dacc[r]));
            if (s >= 0.1f) atomicOr(&maskbuf[n], 1u << tt);
        }
    }
    __syncthreads();
    if (tid < 64) {
        int bn = bn0 + tid;
        unsigned m = maskbuf[tid];
        float deg = 1.0f + (float)g_indeg[bn] + (float)__popc(m);
        float is = rsqrtf(deg);
        g_mask[bn] = m;
        g_invs[bn] = is;
        invsS[tid] = is;
    }
    __syncthreads();
    {
        unsigned* A32 = (unsigned*)g_A;
        int r0 = m0 + ty, r1 = r0 + 8;
        float s0 = invsS[r0], s1 = invsS[r1];
        int cb = (h0 >> 1) + tk;
        #pragma unroll
        for (int ns = 0; ns < 4; ns++) {
            A32[(bn0+r0)*32 + cb + ns*4] = pack_bf16x2(acc[ns][0]*s0, acc[ns][1]*s0);
            A32[(bn0+r1)*32 + cb + ns*4] = pack_bf16x2(acc[ns][2]*s1, acc[ns][3]*s1);
        }
    }
}

// ------- per-graph source weights + token-mask sums -------------------------
__global__ void wtok_kernel(const int* __restrict__ esrc, const int* __restrict__ edst)
{
    __shared__ float invs_s[Nn];
    __shared__ float w_s[Nn];
    __shared__ float tm[Tt];
    int g = blockIdx.x, tid = threadIdx.x;
    int lane = tid & 31;
    invs_s[tid] = g_invs[g*Nn + tid];
    w_s[tid] = 0.f;
    if (tid < Tt) tm[tid] = 0.f;
    __syncthreads();
    const int* sp = esrc + g*Ee;
    const int* dp = edst + g*Ee;
    for (int e = tid; e < Ee; e += Nn)
        atomicAdd(&w_s[sp[e]], invs_s[dp[e]]);
    {
        unsigned m = g_mask[g*Nn + tid];
        float v = invs_s[tid];
        #pragma unroll
        for (int t = 0; t < Tt; t++) {
            float p = ((m >> t) & 1u) ? v : 0.f;
            #pragma unroll
            for (int d = 16; d > 0; d >>= 1)
                p += __shfl_xor_sync(0xffffffffu, p, d);
            if (lane == 0) atomicAdd(&tm[t], p);
        }
    }
    __syncthreads();
    g_w[g*Nn + tid] = invs_s[tid]*(w_s[tid] + invs_s[tid]);
    if (tid < Tt) g_tm[g*Tt + tid] = tm[tid];
}

// ---- gather core: R4/R6 proven load pattern (scalar idx, fp32 accumulate) --
__device__ __forceinline__ float4 gather_node(const uint2* __restrict__ A2,
                                              int bn, int l16, int half)
{
    int cnt = g_indeg[bn];
    int off = g_off[bn];
    float4 acc = make_float4(0.f, 0.f, 0.f, 0.f);
    int e = 0;
    for (; e + 8 <= cnt; e += 8) {
        int i0 = __ldg(&g_csr[off + e     + half]);
        int i1 = __ldg(&g_csr[off + e + 2 + half]);
        int i2 = __ldg(&g_csr[off + e + 4 + half]);
        int i3 = __ldg(&g_csr[off + e + 6 + half]);
        uint2 v0 = __ldg(&A2[i0*16 + l16]);
        uint2 v1 = __ldg(&A2[i1*16 + l16]);
        uint2 v2 = __ldg(&A2[i2*16 + l16]);
        uint2 v3 = __ldg(&A2[i3*16 + l16]);
        acc_bf16x4(acc, v0); acc_bf16x4(acc, v1);
        acc_bf16x4(acc, v2); acc_bf16x4(acc, v3);
    }
    for (; e + 2 <= cnt; e += 2) {
        int i0 = __ldg(&g_csr[off + e + half]);
        uint2 v0 = __ldg(&A2[i0*16 + l16]);
        acc_bf16x4(acc, v0);
    }
    if (e < cnt && half == 0) {
        int i0 = __ldg(&g_csr[off + e]);
        uint2 v0 = __ldg(&A2[i0*16 + l16]);
        acc_bf16x4(acc, v0);
    }
    acc.x += __shfl_xor_sync(0xffffffffu, acc.x, 16);
    acc.y += __shfl_xor_sync(0xffffffffu, acc.y, 16);
    acc.z += __shfl_xor_sync(0xffffffffu, acc.z, 16);
    acc.w += __shfl_xor_sync(0xffffffffu, acc.w, 16);
    return acc;
}

// ------- agg1: layer-1 gather + act + weighted pool (512 thr, 16 nodes) -----
__global__ void agg1_kernel(const float* __restrict__ b1)
{
    __shared__ float4 st[Tt*16];
    __shared__ float4 bias[16];
    __shared__ float sum[Hh];
    int tid = threadIdx.x;
    const float4* s1p = (const float4*)g_st1;
    for (int i = tid; i < Tt*16; i += 512) st[i] = s1p[i];
    if (tid < 16) bias[tid] = ((const float4*)b1)[tid];
    if (tid < Hh) sum[tid] = 0.f;
    __syncthreads();
    int lane = tid & 31;
    int l16 = lane & 15, half = lane >> 4;
    int bn = blockIdx.x*16 + (tid >> 5);
    float4 acc = gather_node((const uint2*)g_A, bn, l16, half);
    if (half == 0) {
        unsigned mk = g_mask[bn];
        while (mk) {
            int t = __ffs(mk) - 1; mk &= mk - 1;
            float4 v = st[t*16 + l16];
            acc.x += v.x; acc.y += v.y; acc.z += v.z; acc.w += v.w;
        }
        uint2 sv = ((const uint2*)g_A)[bn*16 + l16];
        acc_bf16x4(acc, sv);
        float is = g_invs[bn];
        float4 bb = bias[l16];
        float4 o;
        o.x = acc.x*is + bb.x; o.y = acc.y*is + bb.y;
        o.z = acc.z*is + bb.z; o.w = acc.w*is + bb.w;
        o.x = (o.x >= 0.f) ? o.x : 0.01f*o.x;
        o.y = (o.y >= 0.f) ? o.y : 0.01f*o.y;
        o.z = (o.z >= 0.f) ? o.z : 0.01f*o.z;
        o.w = (o.w >= 0.f) ? o.w : 0.01f*o.w;
        float fw = g_w[bn];
        atomicAdd(&sum[l16*4+0], o.x*fw);
        atomicAdd(&sum[l16*4+1], o.y*fw);
        atomicAdd(&sum[l16*4+2], o.z*fw);
        atomicAdd(&sum[l16*4+3], o.w*fw);
    }
    __syncthreads();
    if (tid < Hh) {
        int b = blockIdx.x >> 6;            // 64 blocks per graph
        atomicAdd(&g_P[b*Hh + tid], sum[tid]);
    }
}

// ------- head: add token-cross, W2 matvec, b2/toksum, pool, softmax ---------
__global__ void head_kernel(const float* __restrict__ W2, const float* __restrict__ b2,
                            const float* __restrict__ Wa, const float* __restrict__ ba,
                            float* __restrict__ out)
{
    __shared__ float P[Hh];
    __shared__ float emb[Hh];
    __shared__ float tm[Tt];
    int g = blockIdx.x, h = threadIdx.x;
    if (h < Tt) tm[h] = g_tm[g*Tt + h];
    __syncthreads();
    float p = g_P[g*Hh + h];
    #pragma unroll
    for (int t = 0; t < Tt; t++) p += g_st2p[t*Hh + h]*tm[t];
    P[h] = p;
    __syncthreads();
    const float scale = 1.f/(float)(Tt + Nn);
    float a = 0.f;
    for (int k = 0; k < Hh; k++) a += P[k]*W2[k*Hh + h];
    emb[h] = (a + (float)Nn*b2[h] + g_toksum[h]) * scale;
    __syncthreads();
    if (h == 0) {
        float l0 = ba[0], l1 = ba[1];
        for (int o = 0; o < Hh; o++) {
            l0 += emb[o]*Wa[o*2+0];
            l1 += emb[o]*Wa[o*2+1];
        }
        float mx = fmaxf(l0, l1);
        float e0 = expf(l0 - mx), e1 = expf(l1 - mx);
        float s = e0 + e1;
        out[g*2+0] = e0/s;
        out[g*2+1] = e1/s;
    }
}

// ---------------- launch ----------------------------------------------------
extern "C" void kernel_launch(void* const* d_in, const int* in_sizes, int n_in,
                              void* d_out, int out_size)
{
    const float* x    = (const float*)d_in[0];
    const float* tok  = (const float*)d_in[1];
    const float* W1   = (const float*)d_in[2];
    const float* b1   = (const float*)d_in[3];
    const float* W2   = (const float*)d_in[4];
    const float* b2   = (const float*)d_in[5];
    const float* Wa   = (const float*)d_in[6];
    const float* ba   = (const float*)d_in[7];
    const int*   esrc = (const int*)d_in[8];
    const int*   edst = (const int*)d_in[9];
    float* out = (float*)d_out;

    csr_token_kernel<<<Bq + 1, Nn>>>(esrc, edst, tok, W1, b1, W2, b2);
    xpass_kernel<<<BN/64, 256>>>(x, W1, tok);
    wtok_kernel<<<Bq, Nn>>>(esrc, edst);
    agg1_kernel<<<BN/16, 512>>>(b1);
    head_kernel<<<Bq, Hh>>>(W2, b2, Wa, ba, out);
}